// round 16
// baseline (speedup 1.0000x reference)
#include <cuda_runtime.h>
#include <cstdint>

#define NN 8192

// Scratch (allocation-free rule: __device__ globals)
__device__ float g_conv[NN];
__device__ float g_h[NN];

__device__ __forceinline__ void cp_async16(uint32_t smem_addr, const void* gptr) {
    asm volatile("cp.async.cg.shared.global [%0], [%1], 16;\n"
                 :: "r"(smem_addr), "l"(gptr));
}
__device__ __forceinline__ void cp_commit() {
    asm volatile("cp.async.commit_group;\n");
}
template <int N>
__device__ __forceinline__ void cp_wait() {
    asm volatile("cp.async.wait_group %0;\n" :: "n"(N));
}

// Kernel 1: per-node 16-wide dot + bias + sigmoid (launch-floor bound)
__global__ void __launch_bounds__(64) conv_sigmoid_kernel(
    const float* __restrict__ nf,
    const float* __restrict__ cw,
    const float* __restrict__ cb) {
    int i = blockIdx.x * 64 + threadIdx.x;
    if (i >= NN) return;
    const float4* row = reinterpret_cast<const float4*>(nf + (size_t)i * 16);
    float4 w0 = reinterpret_cast<const float4*>(cw)[0];
    float4 w1 = reinterpret_cast<const float4*>(cw)[1];
    float4 w2 = reinterpret_cast<const float4*>(cw)[2];
    float4 w3 = reinterpret_cast<const float4*>(cw)[3];
    float4 a0 = row[0], a1 = row[1], a2 = row[2], a3 = row[3];
    float s = a0.x*w0.x + a0.y*w0.y + a0.z*w0.z + a0.w*w0.w
            + a1.x*w1.x + a1.y*w1.y + a1.z*w1.z + a1.w*w1.w
            + a2.x*w2.x + a2.y*w2.y + a2.z*w2.z + a2.w*w2.w
            + a3.x*w3.x + a3.y*w3.y + a3.z*w3.z + a3.w*w3.w;
    s += cb[0];
    g_conv[i] = 1.0f / (1.0f + __expf(-s));
}

// Matvec (R6 form, best so far) + PDL: the block queues its whole 32KB W row
// via cp.async (no dependency on upstream kernel), THEN waits on the upstream
// grid via cudaGridDependencySynchronize() before reading x. With the PSS
// launch attribute, these blocks start while the upstream kernel is still
// draining, so the W prefetch overlaps the conv kernel / previous matvec tail.
template <int APPLY_TANH>
__global__ void __launch_bounds__(256) matvec_kernel(
    const float* __restrict__ W,
    const float* __restrict__ b,
    const float* __restrict__ x,
    float* __restrict__ y) {
    __shared__ float4 buf[NN / 4];  // 32 KB
    __shared__ float red[8];

    const int row = blockIdx.x;
    const int tid = threadIdx.x;
    const float4* __restrict__ W4 = reinterpret_cast<const float4*>(W + (size_t)row * NN);
    const float4* __restrict__ x4 = reinterpret_cast<const float4*>(x);
    const uint32_t sbase = (uint32_t)__cvta_generic_to_shared(buf);

    #pragma unroll
    for (int j = 0; j < 4; ++j) {
        int i = tid + 256 * j;
        cp_async16(sbase + i * 16, W4 + i);
    }
    cp_commit();
    #pragma unroll
    for (int j = 4; j < 8; ++j) {
        int i = tid + 256 * j;
        cp_async16(sbase + i * 16, W4 + i);
    }
    cp_commit();

    // Wait for the upstream kernel's stores to be visible before reading x.
    cudaGridDependencySynchronize();

    float s = 0.0f;
    cp_wait<1>();
    #pragma unroll
    for (int j = 0; j < 4; ++j) {
        int i = tid + 256 * j;
        float4 a = buf[i];
        float4 v = x4[i];
        s += a.x * v.x + a.y * v.y + a.z * v.z + a.w * v.w;
    }
    cp_wait<0>();
    #pragma unroll
    for (int j = 4; j < 8; ++j) {
        int i = tid + 256 * j;
        float4 a = buf[i];
        float4 v = x4[i];
        s += a.x * v.x + a.y * v.y + a.z * v.z + a.w * v.w;
    }

    #pragma unroll
    for (int o = 16; o > 0; o >>= 1) s += __shfl_xor_sync(0xffffffffu, s, o);
    if ((tid & 31) == 0) red[tid >> 5] = s;
    __syncthreads();
    if (tid < 8) {
        s = red[tid];
        #pragma unroll
        for (int o = 4; o > 0; o >>= 1) s += __shfl_xor_sync(0x000000ffu, s, o);
        if (tid == 0) {
            s += b[row];
            y[row] = APPLY_TANH ? tanhf(s) : s;
        }
    }
}

extern "C" void kernel_launch(void* const* d_in, const int* in_sizes, int n_in,
                              void* d_out, int out_size) {
    const float* node_features = (const float*)d_in[0]; // (8192, 16)
    const float* conv_w        = (const float*)d_in[1]; // (16,)
    const float* conv_b        = (const float*)d_in[2]; // scalar
    const float* W1            = (const float*)d_in[3]; // (8192, 8192)
    const float* b1            = (const float*)d_in[4]; // (8192,)
    const float* W2            = (const float*)d_in[5]; // (8192, 8192)
    const float* b2            = (const float*)d_in[6]; // (8192,)
    float* out = (float*)d_out;

    float* conv_feats;
    float* h;
    cudaGetSymbolAddress((void**)&conv_feats, g_conv);
    cudaGetSymbolAddress((void**)&h, g_h);

    conv_sigmoid_kernel<<<NN / 64, 64>>>(node_features, conv_w, conv_b);

    // PDL launches: allow each matvec to start (and prefetch W) while the
    // upstream kernel is still completing.
    cudaLaunchAttribute attrs[1];
    attrs[0].id = cudaLaunchAttributeProgrammaticStreamSerialization;
    attrs[0].val.programmaticStreamSerializationAllowed = 1;

    cudaLaunchConfig_t cfg = {};
    cfg.gridDim = dim3(NN);
    cfg.blockDim = dim3(256);
    cfg.dynamicSmemBytes = 0;
    cfg.stream = 0;
    cfg.attrs = attrs;
    cfg.numAttrs = 1;

    cudaLaunchKernelEx(&cfg, matvec_kernel<1>, W1, b1,
                       (const float*)conv_feats, h);
    cudaLaunchKernelEx(&cfg, matvec_kernel<0>, W2, b2,
                       (const float*)h, out);
}